// round 4
// baseline (speedup 1.0000x reference)
#include <cuda_runtime.h>
#include <math.h>

// Problem shape (fixed by setup_inputs): B=2, L=10000, H=8, E=64, NE=160000.
// L and NE are re-derived from in_sizes; B/H/E are hardcoded.
#define B_CONST 2
#define H_CONST 8
#define E_CONST 64
#define L_MAX   10000
#define NE_MAX  160000
#define ROW_STRIDE (H_CONST * E_CONST)   // 512 floats between consecutive L rows

// Fixed device scratch (no allocation allowed).
__device__ int g_deg[L_MAX];
__device__ int g_off[L_MAX + 1];
__device__ int g_cursor[L_MAX];
__device__ int g_src[NE_MAX];
__device__ int g_edge_dst[NE_MAX];
__device__ int g_edge_src[NE_MAX];
__device__ int g_is64;

// ---------------------------------------------------------------------------
// adj dtype probe: reference declares int64, but JAX without x64 emits int32.
// Viewed as int32 words: int64 data (values < 2^31) has ALL odd words == 0;
// int32 data has random edge ids at odd words. OR-reduce 2048 words decides.
// ---------------------------------------------------------------------------
__global__ void detect_kernel(const int* __restrict__ buf, int NE) {
    // single block, 256 threads
    __shared__ int s_or;
    if (threadIdx.x == 0) s_or = 0;
    __syncthreads();
    int acc = 0;
    int nwords = 2 * NE;            // safe lower bound on buffer length in words
    for (int i = threadIdx.x; i < 2048 && 2 * i + 1 < nwords; i += blockDim.x)
        acc |= buf[2 * i + 1];      // odd int32 words
    atomicOr(&s_or, acc);
    __syncthreads();
    if (threadIdx.x == 0) g_is64 = (s_or == 0) ? 1 : 0;
}

__global__ void extract_kernel(const void* __restrict__ adj, int NE, int L) {
    int e = blockIdx.x * blockDim.x + threadIdx.x;
    if (e >= NE) return;
    int d, s;
    if (g_is64) {
        const long long* a = (const long long*)adj;
        d = (int)a[e];
        s = (int)a[NE + e];
    } else {
        const int* a = (const int*)adj;
        d = a[e];
        s = a[NE + e];
    }
    // clamp defensively: valid inputs are in [0, L)
    d = min(max(d, 0), L - 1);
    s = min(max(s, 0), L - 1);
    g_edge_dst[e] = d;
    g_edge_src[e] = s;
}

// ---------------------------------------------------------------------------
// CSR construction
// ---------------------------------------------------------------------------
__global__ void zero_kernel(int L) {
    int i = blockIdx.x * blockDim.x + threadIdx.x;
    if (i < L) { g_deg[i] = 0; g_cursor[i] = 0; }
}

__global__ void hist_kernel(int NE) {
    int e = blockIdx.x * blockDim.x + threadIdx.x;
    if (e < NE) atomicAdd(&g_deg[g_edge_dst[e]], 1);
}

// Single-block exclusive scan over g_deg -> g_off (L up to 10000, 1024 threads).
__global__ void scan_kernel(int L) {
    __shared__ int sh[1024];
    __shared__ int s_base;
    int tid = threadIdx.x;
    if (tid == 0) s_base = 0;
    __syncthreads();
    for (int start = 0; start < L; start += 1024) {
        int i = start + tid;
        int val = (i < L) ? g_deg[i] : 0;
        sh[tid] = val;
        __syncthreads();
        #pragma unroll
        for (int off = 1; off < 1024; off <<= 1) {
            int t = (tid >= off) ? sh[tid - off] : 0;
            __syncthreads();
            if (tid >= off) sh[tid] += t;
            __syncthreads();
        }
        if (i < L) g_off[i] = s_base + sh[tid] - val;   // exclusive prefix
        __syncthreads();
        if (tid == 0) s_base += sh[1023];
        __syncthreads();
    }
    if (tid == 0) g_off[L] = s_base;
}

__global__ void scatter_kernel(int NE) {
    int e = blockIdx.x * blockDim.x + threadIdx.x;
    if (e < NE) {
        int d = g_edge_dst[e];
        int pos = atomicAdd(&g_cursor[d], 1);
        g_src[g_off[d] + pos] = g_edge_src[e];
    }
}

// ---------------------------------------------------------------------------
// Fused sparse attention: one block per dst node, one warp per (b,h) channel.
// Online softmax + fused V accumulation, single pass over the edge list.
// ---------------------------------------------------------------------------
#define SMEM_EDGES 2048

__global__ __launch_bounds__(512) void attn_kernel(
    const float* __restrict__ q, const float* __restrict__ k,
    const float* __restrict__ v, float* __restrict__ out, int L) {

    __shared__ int ssrc[SMEM_EDGES];

    int node = blockIdx.x;
    int off  = g_off[node];
    int deg  = g_off[node + 1] - off;
    int cached = deg < SMEM_EDGES ? deg : SMEM_EDGES;

    for (int i = threadIdx.x; i < cached; i += blockDim.x)
        ssrc[i] = g_src[off + i];
    __syncthreads();

    int warp = threadIdx.x >> 5;        // 0..15 -> (b,h) channel
    int lane = threadIdx.x & 31;
    int b = warp >> 3;                  // 0..1
    int h = warp & 7;                   // 0..7

    // q row for this (b, node, h): 64 floats, 2 per lane.
    const float* qrow = q + ((size_t)(b * L + node) * H_CONST + h) * E_CONST;
    float2 qv = *(const float2*)(qrow + lane * 2);

    // Base pointers so that row for source s is base + s * ROW_STRIDE.
    const float* kbase = k + ((size_t)b * L * H_CONST + h) * E_CONST + lane * 2;
    const float* vbase = v + ((size_t)b * L * H_CONST + h) * E_CONST + lane * 2;

    float m = -INFINITY;
    float s = 0.f;
    float ax = 0.f, ay = 0.f;
    const float temp = 0.125f;          // 1/sqrt(64)

    int i = 0;
    // 2-edge unroll: 4 independent L2 loads in flight per iteration.
    for (; i + 2 <= deg; i += 2) {
        int s0 = (i     < cached) ? ssrc[i]     : g_src[off + i];
        int s1 = (i + 1 < cached) ? ssrc[i + 1] : g_src[off + i + 1];
        float2 k0 = *(const float2*)(kbase + (size_t)s0 * ROW_STRIDE);
        float2 k1 = *(const float2*)(kbase + (size_t)s1 * ROW_STRIDE);
        float2 v0 = *(const float2*)(vbase + (size_t)s0 * ROW_STRIDE);
        float2 v1 = *(const float2*)(vbase + (size_t)s1 * ROW_STRIDE);

        float d0 = qv.x * k0.x + qv.y * k0.y;
        float d1 = qv.x * k1.x + qv.y * k1.y;
        #pragma unroll
        for (int o = 16; o >= 1; o >>= 1) {
            d0 += __shfl_xor_sync(0xffffffffu, d0, o);
            d1 += __shfl_xor_sync(0xffffffffu, d1, o);
        }
        float x0 = d0 * temp;
        float x1 = d1 * temp;

        float mn = fmaxf(m, x0);
        float sc = __expf(m - mn);
        float p0 = __expf(x0 - mn);
        s  = s  * sc + p0;
        ax = ax * sc + p0 * v0.x;
        ay = ay * sc + p0 * v0.y;
        m = mn;

        mn = fmaxf(m, x1);
        sc = __expf(m - mn);
        float p1 = __expf(x1 - mn);
        s  = s  * sc + p1;
        ax = ax * sc + p1 * v1.x;
        ay = ay * sc + p1 * v1.y;
        m = mn;
    }
    if (i < deg) {
        int s0 = (i < cached) ? ssrc[i] : g_src[off + i];
        float2 k0 = *(const float2*)(kbase + (size_t)s0 * ROW_STRIDE);
        float2 v0 = *(const float2*)(vbase + (size_t)s0 * ROW_STRIDE);
        float d0 = qv.x * k0.x + qv.y * k0.y;
        #pragma unroll
        for (int o = 16; o >= 1; o >>= 1)
            d0 += __shfl_xor_sync(0xffffffffu, d0, o);
        float x0 = d0 * temp;
        float mn = fmaxf(m, x0);
        float sc = __expf(m - mn);
        float p0 = __expf(x0 - mn);
        s  = s  * sc + p0;
        ax = ax * sc + p0 * v0.x;
        ay = ay * sc + p0 * v0.y;
        m = mn;
    }

    // out = sum(exp * v) / (sum(exp) + 1e-16); deg==0 -> exact zeros.
    float inv = 1.f / (s + 1e-16f);
    float2 o2 = make_float2(ax * inv, ay * inv);
    *(float2*)(out + ((size_t)(b * L + node) * H_CONST + h) * E_CONST + lane * 2) = o2;
}

// ---------------------------------------------------------------------------
// Launch
// ---------------------------------------------------------------------------
extern "C" void kernel_launch(void* const* d_in, const int* in_sizes, int n_in,
                              void* d_out, int out_size) {
    const float* q = (const float*)d_in[0];
    const float* k = (const float*)d_in[1];
    const float* v = (const float*)d_in[2];
    const void*  adj = d_in[3];

    int NE = in_sizes[3] / 2;                               // adj is [2, NE]
    int L  = in_sizes[0] / (B_CONST * H_CONST * E_CONST);   // queries [B,L,H,E]
    float* out = (float*)d_out;

    detect_kernel<<<1, 256>>>((const int*)adj, NE);
    extract_kernel<<<(NE + 255) / 256, 256>>>(adj, NE, L);
    zero_kernel<<<(L + 255) / 256, 256>>>(L);
    hist_kernel<<<(NE + 255) / 256, 256>>>(NE);
    scan_kernel<<<1, 1024>>>(L);
    scatter_kernel<<<(NE + 255) / 256, 256>>>(NE);
    attn_kernel<<<L, 512>>>(q, k, v, out, L);
}

// round 5
// speedup vs baseline: 1.1292x; 1.1292x over previous
#include <cuda_runtime.h>
#include <math.h>

// Problem shape (fixed by setup_inputs): B=2, L=10000, H=8, E=64, NE=160000.
// L and NE are re-derived from in_sizes; B/H/E are hardcoded.
#define B_CONST 2
#define H_CONST 8
#define E_CONST 64
#define L_MAX   10000
#define NE_MAX  160000
#define ROW_STRIDE (H_CONST * E_CONST)   // 512 floats between consecutive L rows

// Fixed device scratch (no allocation allowed).
__device__ int g_deg[L_MAX];
__device__ int g_off[L_MAX + 1];
__device__ int g_cursor[L_MAX];
__device__ int g_src[NE_MAX];
__device__ int g_edge_dst[NE_MAX];
__device__ int g_edge_src[NE_MAX];
__device__ int g_is64;

// ---------------------------------------------------------------------------
// K1: zero counters (grid-stride, all blocks) + adj dtype probe (block 0).
// Probe: reference declares int64, but JAX without x64 emits int32. Viewed as
// int32 words, int64 data (values < 2^31) has ALL odd words == 0; int32 data
// has random edge ids there. OR-reduce of 2048 odd words decides.
// ---------------------------------------------------------------------------
__global__ void zero_detect_kernel(const int* __restrict__ buf, int NE, int L) {
    int stride = gridDim.x * blockDim.x;
    for (int i = blockIdx.x * blockDim.x + threadIdx.x; i < L; i += stride) {
        g_deg[i] = 0;
        g_cursor[i] = 0;
    }
    if (blockIdx.x == 0) {
        __shared__ int s_or;
        if (threadIdx.x == 0) s_or = 0;
        __syncthreads();
        int acc = 0;
        int nwords = 2 * NE;            // safe lower bound on buffer length in words
        for (int i = threadIdx.x; i < 2048 && 2 * i + 1 < nwords; i += blockDim.x)
            acc |= buf[2 * i + 1];
        atomicOr(&s_or, acc);
        __syncthreads();
        if (threadIdx.x == 0) g_is64 = (s_or == 0) ? 1 : 0;
    }
}

// ---------------------------------------------------------------------------
// K2: extract edges (dtype-dispatched, clamped) + degree histogram, one pass.
// ---------------------------------------------------------------------------
__global__ void extract_hist_kernel(const void* __restrict__ adj, int NE, int L) {
    int e = blockIdx.x * blockDim.x + threadIdx.x;
    if (e >= NE) return;
    int d, s;
    if (g_is64) {
        const long long* a = (const long long*)adj;
        d = (int)a[e];
        s = (int)a[NE + e];
    } else {
        const int* a = (const int*)adj;
        d = a[e];
        s = a[NE + e];
    }
    d = min(max(d, 0), L - 1);   // defensive clamp; valid inputs unaffected
    s = min(max(s, 0), L - 1);
    g_edge_dst[e] = d;
    g_edge_src[e] = s;
    atomicAdd(&g_deg[d], 1);
}

// ---------------------------------------------------------------------------
// K3: exclusive scan g_deg -> g_off. Single block of 1024 threads; each thread
// serially owns ITEMS contiguous elements, then a shuffle-based block scan of
// the 1024 thread-sums (3 __syncthreads total).
// ---------------------------------------------------------------------------
__global__ void scan_kernel(int L) {
    __shared__ int warp_sums[32];
    const int tid = threadIdx.x;
    const int lane = tid & 31;
    const int w = tid >> 5;
    const int ITEMS = (L + 1023) / 1024;

    int base = tid * ITEMS;
    int local[16];                       // ITEMS <= 16 for L <= 16384
    int lsum = 0;
    #pragma unroll 4
    for (int j = 0; j < ITEMS; j++) {
        int idx = base + j;
        int v = (idx < L) ? g_deg[idx] : 0;
        local[j] = lsum;                 // local exclusive prefix
        lsum += v;
    }

    // inclusive warp scan of lsum
    int val = lsum;
    #pragma unroll
    for (int o = 1; o < 32; o <<= 1) {
        int n = __shfl_up_sync(0xffffffffu, val, o);
        if (lane >= o) val += n;
    }
    if (lane == 31) warp_sums[w] = val;
    __syncthreads();
    if (w == 0) {
        int sv = warp_sums[lane];
        #pragma unroll
        for (int o = 1; o < 32; o <<= 1) {
            int n = __shfl_up_sync(0xffffffffu, sv, o);
            if (lane >= o) sv += n;
        }
        warp_sums[lane] = sv;            // inclusive warp-total prefix
    }
    __syncthreads();
    int excl = val - lsum + (w > 0 ? warp_sums[w - 1] : 0);  // thread-exclusive

    #pragma unroll 4
    for (int j = 0; j < ITEMS; j++) {
        int idx = base + j;
        if (idx < L) g_off[idx] = excl + local[j];
    }
    if (tid == 1023) g_off[L] = excl + lsum;
}

// ---------------------------------------------------------------------------
// K4: scatter src indices into CSR slots.
// ---------------------------------------------------------------------------
__global__ void scatter_kernel(int NE) {
    int e = blockIdx.x * blockDim.x + threadIdx.x;
    if (e < NE) {
        int d = g_edge_dst[e];
        int pos = atomicAdd(&g_cursor[d], 1);
        g_src[g_off[d] + pos] = g_edge_src[e];
    }
}

// ---------------------------------------------------------------------------
// K5: fused sparse attention. One block per dst node, one warp per (b,h)
// channel; online softmax + fused V accumulation in a single edge pass.
// ---------------------------------------------------------------------------
#define SMEM_EDGES 2048

__global__ __launch_bounds__(512) void attn_kernel(
    const float* __restrict__ q, const float* __restrict__ k,
    const float* __restrict__ v, float* __restrict__ out, int L) {

    __shared__ int ssrc[SMEM_EDGES];

    int node = blockIdx.x;
    int off  = g_off[node];
    int deg  = g_off[node + 1] - off;
    bool fits = (deg <= SMEM_EDGES);
    int cached = fits ? deg : SMEM_EDGES;

    for (int i = threadIdx.x; i < cached; i += blockDim.x)
        ssrc[i] = g_src[off + i];
    __syncthreads();

    int warp = threadIdx.x >> 5;        // 0..15 -> (b,h) channel
    int lane = threadIdx.x & 31;
    int b = warp >> 3;
    int h = warp & 7;

    const float* qrow = q + ((size_t)(b * L + node) * H_CONST + h) * E_CONST;
    float2 qv = *(const float2*)(qrow + lane * 2);

    const float* kbase = k + ((size_t)b * L * H_CONST + h) * E_CONST + lane * 2;
    const float* vbase = v + ((size_t)b * L * H_CONST + h) * E_CONST + lane * 2;

    float m = -INFINITY;
    float s = 0.f;
    float ax = 0.f, ay = 0.f;
    const float temp = 0.125f;          // 1/sqrt(64)

    int i = 0;
    if (fits) {
        // Common case: whole edge list in smem, no per-iteration predicate.
        for (; i + 2 <= deg; i += 2) {
            int s0 = ssrc[i];
            int s1 = ssrc[i + 1];
            float2 k0 = *(const float2*)(kbase + (size_t)s0 * ROW_STRIDE);
            float2 k1 = *(const float2*)(kbase + (size_t)s1 * ROW_STRIDE);
            float2 v0 = *(const float2*)(vbase + (size_t)s0 * ROW_STRIDE);
            float2 v1 = *(const float2*)(vbase + (size_t)s1 * ROW_STRIDE);

            float d0 = qv.x * k0.x + qv.y * k0.y;
            float d1 = qv.x * k1.x + qv.y * k1.y;
            #pragma unroll
            for (int o = 16; o >= 1; o >>= 1) {
                d0 += __shfl_xor_sync(0xffffffffu, d0, o);
                d1 += __shfl_xor_sync(0xffffffffu, d1, o);
            }
            float x0 = d0 * temp;
            float x1 = d1 * temp;

            float mn = fmaxf(m, x0);
            float sc = __expf(m - mn);
            float p0 = __expf(x0 - mn);
            s  = s  * sc + p0;
            ax = ax * sc + p0 * v0.x;
            ay = ay * sc + p0 * v0.y;
            m = mn;

            mn = fmaxf(m, x1);
            sc = __expf(m - mn);
            float p1 = __expf(x1 - mn);
            s  = s  * sc + p1;
            ax = ax * sc + p1 * v1.x;
            ay = ay * sc + p1 * v1.y;
            m = mn;
        }
    }
    // Tail / smem-overflow path (also handles odd last edge of the fast path).
    for (; i < deg; i++) {
        int s0 = (i < cached) ? ssrc[i] : g_src[off + i];
        float2 k0 = *(const float2*)(kbase + (size_t)s0 * ROW_STRIDE);
        float2 v0 = *(const float2*)(vbase + (size_t)s0 * ROW_STRIDE);
        float d0 = qv.x * k0.x + qv.y * k0.y;
        #pragma unroll
        for (int o = 16; o >= 1; o >>= 1)
            d0 += __shfl_xor_sync(0xffffffffu, d0, o);
        float x0 = d0 * temp;
        float mn = fmaxf(m, x0);
        float sc = __expf(m - mn);
        float p0 = __expf(x0 - mn);
        s  = s  * sc + p0;
        ax = ax * sc + p0 * v0.x;
        ay = ay * sc + p0 * v0.y;
        m = mn;
    }

    // out = sum(exp * v) / (sum(exp) + 1e-16); deg==0 -> exact zeros.
    float inv = 1.f / (s + 1e-16f);
    float2 o2 = make_float2(ax * inv, ay * inv);
    *(float2*)(out + ((size_t)(b * L + node) * H_CONST + h) * E_CONST + lane * 2) = o2;
}

// ---------------------------------------------------------------------------
// Launch: 5 graph nodes.
// ---------------------------------------------------------------------------
extern "C" void kernel_launch(void* const* d_in, const int* in_sizes, int n_in,
                              void* d_out, int out_size) {
    const float* q = (const float*)d_in[0];
    const float* k = (const float*)d_in[1];
    const float* v = (const float*)d_in[2];
    const void*  adj = d_in[3];

    int NE = in_sizes[3] / 2;                               // adj is [2, NE]
    int L  = in_sizes[0] / (B_CONST * H_CONST * E_CONST);   // queries [B,L,H,E]
    float* out = (float*)d_out;

    zero_detect_kernel<<<40, 256>>>((const int*)adj, NE, L);
    extract_hist_kernel<<<(NE + 255) / 256, 256>>>(adj, NE, L);
    scan_kernel<<<1, 1024>>>(L);
    scatter_kernel<<<(NE + 255) / 256, 256>>>(NE);
    attn_kernel<<<L, 512>>>(q, k, v, out, L);
}